// round 3
// baseline (speedup 1.0000x reference)
#include <cuda_runtime.h>
#include <math.h>

#define BATCH 32
#define CIN   256
#define OCH   256
#define HW    56
#define NPIX  (HW*HW)           // 3136
#define GAPN  16
#define MOCH  512
#define FC2   589824            // OCH*CIN*9
#define PERG  1152

// device scratch (allowed: static __device__ globals, no runtime allocation)
__device__ float g_gap[BATCH*CIN];
__device__ float g_a[BATCH*MOCH];
__device__ float g_wk[(size_t)BATCH*FC2];   // ~75.5 MB

// ---------------------------------------------------------------------------
// Kernel A: global average pool. One warp per (b,c); 3136 = 98*32 exactly.
// ---------------------------------------------------------------------------
__global__ void gap_kernel(const float* __restrict__ x) {
    int warp = (blockIdx.x * blockDim.x + threadIdx.x) >> 5;
    int lane = threadIdx.x & 31;
    if (warp >= BATCH*CIN) return;
    const float* p = x + (size_t)warp * NPIX;
    float s = 0.f;
#pragma unroll
    for (int i = 0; i < 98; i++) s += p[lane + i*32];
#pragma unroll
    for (int o = 16; o > 0; o >>= 1) s += __shfl_xor_sync(0xffffffffu, s, o);
    if (lane == 0) g_gap[warp] = s * (1.0f / (float)NPIX);
}

// ---------------------------------------------------------------------------
// Kernel B: g = gap @ reduce_w^T + reduce_b ; a = sigmoid(g @ fc1_w^T)
// One block, 512 threads. Tiny.
// ---------------------------------------------------------------------------
__global__ void se_kernel(const float* __restrict__ reduce_w,
                          const float* __restrict__ reduce_b,
                          const float* __restrict__ fc1_w) {
    __shared__ float sg[BATCH*GAPN];
    int tid = threadIdx.x;  // 0..511
    {
        int b = tid >> 4, j = tid & 15;
        float s = reduce_b[j];
        const float* gp = g_gap + b*CIN;
        const float* wp = reduce_w + j*CIN;
#pragma unroll 8
        for (int c = 0; c < CIN; c++) s += gp[c] * wp[c];
        sg[b*GAPN + j] = s;
    }
    __syncthreads();
    {
        int mo = tid;  // 0..511
        float w[GAPN];
#pragma unroll
        for (int j = 0; j < GAPN; j++) w[j] = fc1_w[mo*GAPN + j];
        for (int b = 0; b < BATCH; b++) {
            float s = 0.f;
#pragma unroll
            for (int j = 0; j < GAPN; j++) s += sg[b*GAPN + j] * w[j];
            g_a[b*MOCH + mo] = 1.0f / (1.0f + expf(-s));
        }
    }
}

// ---------------------------------------------------------------------------
// Kernel C: materialize per-sample conv weights.
// wk[b, i] = a[b, i/1152] * fc2_w[i] + fc2_b[i]    (float4-vectorized;
// 1152 % 4 == 0 so a float4 never straddles a group boundary)
// ---------------------------------------------------------------------------
__global__ void wk_kernel(const float* __restrict__ fc2_w,
                          const float* __restrict__ fc2_b) {
    const float4* w4 = (const float4*)fc2_w;
    const float4* b4 = (const float4*)fc2_b;
    float4* o4 = (float4*)g_wk;
    const int per_b4 = FC2 / 4;             // 147456
    int total = BATCH * per_b4;             // 4,718,592
    for (int i = blockIdx.x * blockDim.x + threadIdx.x; i < total;
         i += gridDim.x * blockDim.x) {
        int b  = i / per_b4;
        int r4 = i - b * per_b4;
        float a = g_a[b*MOCH + (r4 >> 2) / (PERG/16)];  // floor(r4/288) == floor(r4*4/1152)
        float4 w = w4[r4], bb = b4[r4], o;
        o.x = fmaf(a, w.x, bb.x);
        o.y = fmaf(a, w.y, bb.y);
        o.z = fmaf(a, w.z, bb.z);
        o.w = fmaf(a, w.w, bb.w);
        o4[i] = o;
    }
}

// ---------------------------------------------------------------------------
// Kernel D: direct 3x3 conv (pad=1), per-batch weights from g_wk.
// Block: (ocb: 32 oc) x (8 rows x 56 cols) for one batch.
// Thread (256 total): tid = p*4 + ocg;  p = prow*8 + pcolg.
//   computes 8 oc x 7 px register tile.  warp == one output row ->
//   x LDS conflict-free (broadcast over the 4 ocg lanes).
// sw padded to stride 73 so the 4 ocg lanes land on distinct banks.
// ---------------------------------------------------------------------------
#define CK   8
#define TH   8
#define OCB  32

__global__ void __launch_bounds__(256, 2)
conv_kernel(const float* __restrict__ x, float* __restrict__ y) {
    __shared__ float sx[CK * 10 * 58];   // 18.56 KB
    __shared__ float sw[OCB * 73];       //  9.13 KB (72 used per row)

    const int b    = blockIdx.z;
    const int ocb  = blockIdx.x;            // 0..7
    const int row0 = blockIdx.y * TH;       // 0..48
    const int tid  = threadIdx.x;
    const int ocg  = tid & 3;               // 0..3  (oc sub-block of 8)
    const int p    = tid >> 2;              // 0..63
    const int prow = p >> 3;                // 0..7  == warp id
    const int col0 = (p & 7) * 7;           // 0,7,...,49

    float acc[8][7];
#pragma unroll
    for (int i = 0; i < 8; i++)
#pragma unroll
        for (int j = 0; j < 7; j++) acc[i][j] = 0.f;

    const float* xb  = x + (size_t)b * CIN * NPIX;
    const float* wkb = g_wk + (size_t)b * FC2 + (size_t)(ocb * OCB) * (CIN * 9);

    for (int cb = 0; cb < CIN; cb += CK) {
        __syncthreads();   // protect smem reads of previous chunk
        // ---- load x tile: CK channels x 10 rows x 58 cols (zero-padded halo)
        for (int idx = tid; idx < CK * 10 * 58; idx += 256) {
            int c   = idx / 580;
            int rem = idx - c * 580;
            int r   = rem / 58;
            int cc  = rem - r * 58;
            int gr  = row0 + r - 1;
            int gc  = cc - 1;
            float v = 0.f;
            if ((unsigned)gr < (unsigned)HW && (unsigned)gc < (unsigned)HW)
                v = xb[(size_t)(cb + c) * NPIX + gr * HW + gc];
            sx[idx] = v;
        }
        // ---- load weights: 32 oc x (CK*9 = 72) contiguous floats each
        for (int idx = tid; idx < OCB * 72; idx += 256) {
            int oc = idx / 72;
            int j  = idx - oc * 72;
            sw[oc * 73 + j] = wkb[(size_t)oc * (CIN * 9) + cb * 9 + j];
        }
        __syncthreads();

        const float* swb = sw + (ocg * 8) * 73;
#pragma unroll
        for (int c = 0; c < CK; c++) {
            const float* sxc = sx + c * 580 + prow * 58 + col0;
#pragma unroll
            for (int kh = 0; kh < 3; kh++) {
                float xr[9];
#pragma unroll
                for (int t = 0; t < 9; t++) xr[t] = sxc[kh * 58 + t];
#pragma unroll
                for (int kw = 0; kw < 3; kw++) {
#pragma unroll
                    for (int oo = 0; oo < 8; oo++) {
                        float w = swb[oo * 73 + c * 9 + kh * 3 + kw];
#pragma unroll
                        for (int j = 0; j < 7; j++)
                            acc[oo][j] = fmaf(w, xr[j + kw], acc[oo][j]);
                    }
                }
            }
        }
    }

    // ---- store 8 oc x 7 px
    const int orow = row0 + prow;
    float* yp = y + (((size_t)b * OCH + ocb * OCB + ocg * 8) * HW + orow) * HW + col0;
#pragma unroll
    for (int oo = 0; oo < 8; oo++)
#pragma unroll
        for (int j = 0; j < 7; j++)
            yp[(size_t)oo * NPIX + j] = acc[oo][j];
}

// ---------------------------------------------------------------------------
extern "C" void kernel_launch(void* const* d_in, const int* in_sizes, int n_in,
                              void* d_out, int out_size) {
    const float* x        = (const float*)d_in[0];
    const float* reduce_w = (const float*)d_in[1];
    const float* reduce_b = (const float*)d_in[2];
    const float* fc1_w    = (const float*)d_in[3];
    const float* fc2_w    = (const float*)d_in[4];
    const float* fc2_b    = (const float*)d_in[5];
    float* y = (float*)d_out;

    // A: GAP  (8192 warps)
    gap_kernel<<<1024, 256>>>(x);
    // B: squeeze-excite MLP
    se_kernel<<<1, 512>>>(reduce_w, reduce_b, fc1_w);
    // C: materialize per-sample weights (4,718,592 float4 = 18432*256)
    wk_kernel<<<18432, 256>>>(fc2_w, fc2_b);
    // D: conv  grid = (oc blocks, row blocks, batch)
    dim3 grid(8, 7, BATCH);
    conv_kernel<<<grid, 256>>>(x, y);
}

// round 5
// speedup vs baseline: 1.1867x; 1.1867x over previous
#include <cuda_runtime.h>
#include <math.h>

#define BATCH 32
#define CIN   256
#define OCH   256
#define HW    56
#define NPIX  (HW*HW)           // 3136
#define GAPN  16
#define MOCH  512
#define FC2   589824            // OCH*CIN*9
#define PERG  1152

// device scratch (allowed: static __device__ globals, no runtime allocation)
__device__ float g_gap[BATCH*CIN];
__device__ float g_a[BATCH*MOCH];
__device__ float g_wk[(size_t)BATCH*FC2];   // ~75.5 MB

// ---- packed fp32x2 helpers (Blackwell FFMA2 path) -------------------------
__device__ __forceinline__ unsigned long long pk_dup(float v) {
    unsigned long long r;
    asm("mov.b64 %0, {%1, %1};" : "=l"(r) : "f"(v));
    return r;
}
__device__ __forceinline__ void fma2(unsigned long long& d,
                                     unsigned long long a,
                                     unsigned long long b) {
    asm("fma.rn.f32x2 %0, %1, %2, %0;" : "+l"(d) : "l"(a), "l"(b));
}
__device__ __forceinline__ void unpk(unsigned long long r, float& lo, float& hi) {
    asm("mov.b64 {%0, %1}, %2;" : "=f"(lo), "=f"(hi) : "l"(r));
}

// ---------------------------------------------------------------------------
// Kernel A: global average pool. One warp per (b,c); 3136 = 98*32 exactly.
// ---------------------------------------------------------------------------
__global__ void gap_kernel(const float* __restrict__ x) {
    int warp = (blockIdx.x * blockDim.x + threadIdx.x) >> 5;
    int lane = threadIdx.x & 31;
    if (warp >= BATCH*CIN) return;
    const float* p = x + (size_t)warp * NPIX;
    float s = 0.f;
#pragma unroll
    for (int i = 0; i < 98; i++) s += p[lane + i*32];
#pragma unroll
    for (int o = 16; o > 0; o >>= 1) s += __shfl_xor_sync(0xffffffffu, s, o);
    if (lane == 0) g_gap[warp] = s * (1.0f / (float)NPIX);
}

// ---------------------------------------------------------------------------
// Kernel B: g = gap @ reduce_w^T + reduce_b ; a = sigmoid(g @ fc1_w^T)
// ---------------------------------------------------------------------------
__global__ void se_kernel(const float* __restrict__ reduce_w,
                          const float* __restrict__ reduce_b,
                          const float* __restrict__ fc1_w) {
    __shared__ float sg[BATCH*GAPN];
    int tid = threadIdx.x;  // 0..511
    {
        int b = tid >> 4, j = tid & 15;
        float s = reduce_b[j];
        const float* gp = g_gap + b*CIN;
        const float* wp = reduce_w + j*CIN;
#pragma unroll 8
        for (int c = 0; c < CIN; c++) s += gp[c] * wp[c];
        sg[b*GAPN + j] = s;
    }
    __syncthreads();
    {
        int mo = tid;  // 0..511
        float w[GAPN];
#pragma unroll
        for (int j = 0; j < GAPN; j++) w[j] = fc1_w[mo*GAPN + j];
        for (int b = 0; b < BATCH; b++) {
            float s = 0.f;
#pragma unroll
            for (int j = 0; j < GAPN; j++) s += sg[b*GAPN + j] * w[j];
            g_a[b*MOCH + mo] = 1.0f / (1.0f + expf(-s));
        }
    }
}

// ---------------------------------------------------------------------------
// Kernel C: materialize per-sample conv weights.
// wk[b, i] = a[b, i/1152] * fc2_w[i] + fc2_b[i]
// ---------------------------------------------------------------------------
__global__ void wk_kernel(const float* __restrict__ fc2_w,
                          const float* __restrict__ fc2_b) {
    const float4* w4 = (const float4*)fc2_w;
    const float4* b4 = (const float4*)fc2_b;
    float4* o4 = (float4*)g_wk;
    const int per_b4 = FC2 / 4;             // 147456
    int total = BATCH * per_b4;             // 4,718,592
    for (int i = blockIdx.x * blockDim.x + threadIdx.x; i < total;
         i += gridDim.x * blockDim.x) {
        int b  = i / per_b4;
        int r4 = i - b * per_b4;
        float a = g_a[b*MOCH + (r4 >> 2) / (PERG/16)];  // floor(r4/288)
        float4 w = w4[r4], bb = b4[r4], o;
        o.x = fmaf(a, w.x, bb.x);
        o.y = fmaf(a, w.y, bb.y);
        o.z = fmaf(a, w.z, bb.z);
        o.w = fmaf(a, w.w, bb.w);
        o4[i] = o;
    }
}

// ---------------------------------------------------------------------------
// Kernel D: direct 3x3 conv (pad=1), FFMA2 (fp32x2) math.
// Block: 32 oc x (8 rows x 56 cols) for one batch. Thread: 4 oc-PAIRS x 7 px.
// Weights stored as float2 {oc_even, oc_odd} interleaved; x broadcast-packed.
// sw2 row stride 73 float2 -> ocg lane stride 584 words = bank offset 8: no
// conflicts on LDS.64. x LDS unchanged (stride-7 banks, 4-lane broadcast).
// ---------------------------------------------------------------------------
#define CK   8
#define TH   8
#define OCB  32

__global__ void __launch_bounds__(256, 2)
conv_kernel(const float* __restrict__ x, float* __restrict__ y) {
    __shared__ float  sx[CK * 10 * 58];          // 18.56 KB
    __shared__ float2 sw2[(OCB/2) * 73];         //  9.34 KB (72 used per row)

    const int b    = blockIdx.z;
    const int ocb  = blockIdx.x;            // 0..7
    const int row0 = blockIdx.y * TH;       // 0..48
    const int tid  = threadIdx.x;
    const int ocg  = tid & 3;               // 0..3  (oc sub-block of 8)
    const int p    = tid >> 2;              // 0..63
    const int prow = p >> 3;                // 0..7  == warp id
    const int col0 = (p & 7) * 7;           // 0,7,...,49

    unsigned long long acc2[4][7];          // 4 oc-pairs x 7 px, packed f32x2
#pragma unroll
    for (int i = 0; i < 4; i++)
#pragma unroll
        for (int j = 0; j < 7; j++) acc2[i][j] = 0ull;

    const float* xb  = x + (size_t)b * CIN * NPIX;
    // pair P (0..15) covers global ocs (ocb*32 + 2P, ocb*32 + 2P + 1)
    const float* wkb = g_wk + (size_t)b * FC2 + (size_t)(ocb * OCB) * (CIN * 9);

    for (int cb = 0; cb < CIN; cb += CK) {
        __syncthreads();   // protect smem reads of previous chunk
        // ---- load x tile: CK channels x 10 rows x 58 cols (zero-padded halo)
        for (int idx = tid; idx < CK * 10 * 58; idx += 256) {
            int c   = idx / 580;
            int rem = idx - c * 580;
            int r   = rem / 58;
            int cc  = rem - r * 58;
            int gr  = row0 + r - 1;
            int gc  = cc - 1;
            float v = 0.f;
            if ((unsigned)gr < (unsigned)HW && (unsigned)gc < (unsigned)HW)
                v = xb[(size_t)(cb + c) * NPIX + gr * HW + gc];
            sx[idx] = v;
        }
        // ---- load weights interleaved by oc-pair: 16 pairs x 72 float2
        for (int idx = tid; idx < (OCB/2) * 72; idx += 256) {
            int P = idx / 72;
            int j = idx - P * 72;
            float w0 = wkb[(size_t)(2*P)     * (CIN*9) + cb*9 + j];
            float w1 = wkb[(size_t)(2*P + 1) * (CIN*9) + cb*9 + j];
            sw2[P * 73 + j] = make_float2(w0, w1);
        }
        __syncthreads();

        const float2* swp = sw2 + (ocg * 4) * 73;   // this thread's 4 pairs
#pragma unroll
        for (int c = 0; c < CK; c++) {
            const float* sxc = sx + c * 580 + prow * 58 + col0;
#pragma unroll
            for (int kh = 0; kh < 3; kh++) {
                unsigned long long xr2[9];
#pragma unroll
                for (int t = 0; t < 9; t++) xr2[t] = pk_dup(sxc[kh * 58 + t]);
#pragma unroll
                for (int kw = 0; kw < 3; kw++) {
#pragma unroll
                    for (int pr = 0; pr < 4; pr++) {
                        float2 wv = swp[pr * 73 + c * 9 + kh * 3 + kw];
                        unsigned long long w2;
                        asm("mov.b64 %0, {%1, %2};" : "=l"(w2)
                            : "f"(wv.x), "f"(wv.y));
#pragma unroll
                        for (int j = 0; j < 7; j++)
                            fma2(acc2[pr][j], w2, xr2[j + kw]);
                    }
                }
            }
        }
    }

    // ---- store: pair pr -> ocs (ocg*8 + 2pr, ocg*8 + 2pr + 1)
    const int orow = row0 + prow;
    float* yp = y + (((size_t)b * OCH + ocb * OCB + ocg * 8) * HW + orow) * HW + col0;
#pragma unroll
    for (int pr = 0; pr < 4; pr++)
#pragma unroll
        for (int j = 0; j < 7; j++) {
            float lo, hi;
            unpk(acc2[pr][j], lo, hi);
            yp[(size_t)(2*pr)     * NPIX + j] = lo;
            yp[(size_t)(2*pr + 1) * NPIX + j] = hi;
        }
}

// ---------------------------------------------------------------------------
extern "C" void kernel_launch(void* const* d_in, const int* in_sizes, int n_in,
                              void* d_out, int out_size) {
    const float* x        = (const float*)d_in[0];
    const float* reduce_w = (const float*)d_in[1];
    const float* reduce_b = (const float*)d_in[2];
    const float* fc1_w    = (const float*)d_in[3];
    const float* fc2_w    = (const float*)d_in[4];
    const float* fc2_b    = (const float*)d_in[5];
    float* y = (float*)d_out;

    gap_kernel<<<1024, 256>>>(x);
    se_kernel<<<1, 512>>>(reduce_w, reduce_b, fc1_w);
    wk_kernel<<<18432, 256>>>(fc2_w, fc2_b);
    dim3 grid(8, 7, BATCH);
    conv_kernel<<<grid, 256>>>(x, y);
}

// round 7
// speedup vs baseline: 2.6961x; 2.2720x over previous
#include <cuda_runtime.h>
#include <cuda_fp16.h>
#include <math.h>
#include <stdint.h>

#define BATCH 32
#define CIN   256
#define OCH   256
#define HW    56
#define NPIX  3136
#define GAPN  16
#define MOCH  512
#define NCK   16          // 16 channel-chunks of 16
#define TAPS  9

// conv CTA tiling: 64 oc x (8 rows x 56 cols) per batch
#define CTA_M 64
#define KPAD  24          // k-dim padded 16->24 halves (conflict-free LDS)

// smem stage layout (bytes)
#define XS_BYTES (10*58*KPAD*2)                 // 27840
#define WS_BYTES (TAPS*CTA_M*KPAD*2)            // 27648
#define OFF_XSH 0
#define OFF_XSL (XS_BYTES)
#define OFF_WSH (2*XS_BYTES)
#define OFF_WSL (2*XS_BYTES + WS_BYTES)
#define STAGE_BYTES (2*XS_BYTES + 2*WS_BYTES)   // 110976
#define SMEM_TOTAL  (2*STAGE_BYTES)             // 221952

__device__ float  g_gap[BATCH*CIN];
__device__ float  g_a[BATCH*MOCH];
__device__ __half g_xth[(size_t)BATCH*NCK*NPIX*16];       // 51.4 MB
__device__ __half g_xtl[(size_t)BATCH*NCK*NPIX*16];
__device__ __half g_wkh[(size_t)BATCH*NCK*TAPS*OCH*16];   // 37.7 MB
__device__ __half g_wkl[(size_t)BATCH*NCK*TAPS*OCH*16];

// ---- helpers --------------------------------------------------------------
__device__ __forceinline__ uint32_t smem_u32(const void* p) {
    uint32_t a;
    asm("{ .reg .u64 t; cvta.to.shared.u64 t, %1; cvt.u32.u64 %0, t; }"
        : "=r"(a) : "l"(p));
    return a;
}
__device__ __forceinline__ void cp16(uint32_t dst, const void* src) {
    asm volatile("cp.async.cg.shared.global [%0], [%1], 16;"
                 :: "r"(dst), "l"(src) : "memory");
}
__device__ __forceinline__ void cp_commit() {
    asm volatile("cp.async.commit_group;" ::: "memory");
}
template <int N>
__device__ __forceinline__ void cp_wait() {
    asm volatile("cp.async.wait_group %0;" :: "n"(N) : "memory");
}
__device__ __forceinline__ void mma16816(float* c, const uint32_t* a,
                                         uint32_t b0, uint32_t b1) {
    asm volatile(
        "mma.sync.aligned.m16n8k16.row.col.f32.f16.f16.f32 "
        "{%0,%1,%2,%3}, {%4,%5,%6,%7}, {%8,%9}, {%0,%1,%2,%3};"
        : "+f"(c[0]), "+f"(c[1]), "+f"(c[2]), "+f"(c[3])
        : "r"(a[0]), "r"(a[1]), "r"(a[2]), "r"(a[3]), "r"(b0), "r"(b1));
}

// ---------------------------------------------------------------------------
// A: global average pool (one warp per (b,c))
// ---------------------------------------------------------------------------
__global__ void gap_kernel(const float* __restrict__ x) {
    int warp = (blockIdx.x * blockDim.x + threadIdx.x) >> 5;
    int lane = threadIdx.x & 31;
    if (warp >= BATCH*CIN) return;
    const float* p = x + (size_t)warp * NPIX;
    float s = 0.f;
#pragma unroll
    for (int i = 0; i < 98; i++) s += p[lane + i*32];
#pragma unroll
    for (int o = 16; o > 0; o >>= 1) s += __shfl_xor_sync(0xffffffffu, s, o);
    if (lane == 0) g_gap[warp] = s * (1.0f / (float)NPIX);
}

// ---------------------------------------------------------------------------
// B: reduce + fc1 + sigmoid
// ---------------------------------------------------------------------------
__global__ void se_kernel(const float* __restrict__ reduce_w,
                          const float* __restrict__ reduce_b,
                          const float* __restrict__ fc1_w) {
    __shared__ float sg[BATCH*GAPN];
    int tid = threadIdx.x;
    {
        int b = tid >> 4, j = tid & 15;
        float s = reduce_b[j];
        const float* gp = g_gap + b*CIN;
        const float* wp = reduce_w + j*CIN;
#pragma unroll 8
        for (int c = 0; c < CIN; c++) s += gp[c] * wp[c];
        sg[b*GAPN + j] = s;
    }
    __syncthreads();
    {
        int mo = tid;
        float w[GAPN];
#pragma unroll
        for (int j = 0; j < GAPN; j++) w[j] = fc1_w[mo*GAPN + j];
        for (int b = 0; b < BATCH; b++) {
            float s = 0.f;
#pragma unroll
            for (int j = 0; j < GAPN; j++) s += sg[b*GAPN + j] * w[j];
            g_a[b*MOCH + mo] = 1.0f / (1.0f + expf(-s));
        }
    }
}

// ---------------------------------------------------------------------------
// C: x transpose to [b][ck][px][c16] fp16 hi/lo
// ---------------------------------------------------------------------------
__global__ void xt_kernel(const float* __restrict__ x) {
    __shared__ float tile[16*225];
    const int rblk = blockIdx.x, ck = blockIdx.y, b = blockIdx.z;
    const int tid = threadIdx.x;
    for (int i = tid; i < 16*224; i += 256) {
        int c = i / 224, p = i - c*224;
        tile[c*225 + p] =
            x[((size_t)(b*CIN) + ck*16 + c)*NPIX + rblk*224 + p];
    }
    __syncthreads();
    size_t base = ((size_t)(b*NCK + ck)*NPIX + rblk*224) * 16;
    for (int i = tid; i < 16*224; i += 256) {
        int p = i >> 4, c = i & 15;
        float v = tile[c*225 + p];
        __half h = __float2half_rn(v);
        __half l = __float2half_rn(v - __half2float(h));
        g_xth[base + p*16 + c] = h;
        g_xtl[base + p*16 + c] = l;
    }
}

// ---------------------------------------------------------------------------
// D: weight materialize to [b][ck][tap][oc][c16] fp16 hi/lo
// ---------------------------------------------------------------------------
__global__ void wk_kernel(const float* __restrict__ fc2_w,
                          const float* __restrict__ fc2_b) {
    size_t idx = (size_t)blockIdx.x * 256 + threadIdx.x;
    int c  = (int)(idx & 15);
    size_t r1 = idx >> 4;
    int oc = (int)(r1 & 255);
    size_t r2 = r1 >> 8;
    int tap = (int)(r2 % 9);
    size_t r3 = r2 / 9;
    int ck = (int)(r3 & 15);
    int b  = (int)(r3 >> 4);
    int cg = ck*16 + c;
    float a = g_a[b*MOCH + 2*oc + (cg >= 128 ? 1 : 0)];
    int f = oc*2304 + cg*9 + tap;
    float w = fmaf(a, fc2_w[f], fc2_b[f]);
    __half h = __float2half_rn(w);
    __half l = __float2half_rn(w - __half2float(h));
    g_wkh[idx] = h;
    g_wkl[idx] = l;
}

// ---------------------------------------------------------------------------
// E: tensor-core conv. grid (4 ocq, 7 rowgrp, 32 b), 256 thr.
// ---------------------------------------------------------------------------
__device__ __forceinline__ void issue_chunk(int b, int ck, int rowbase,
                                            int oc0, int tid, uint32_t stg) {
    // x: 10 rows x 56 cols x (2 half16) ; skip invalid rows (stay zero)
    size_t xbase = ((size_t)(b*NCK + ck)) * NPIX * 16;
    for (int i = tid; i < 10*56*2; i += 256) {
        int r = i / 112, rem = i - r*112;
        int j = rem >> 1, hf = rem & 1;
        int ar = rowbase + r - 1;
        if ((unsigned)ar < (unsigned)HW) {
            size_t s = xbase + ((size_t)ar*HW + j)*16 + hf*8;
            uint32_t d = stg + (uint32_t)((r*(58*KPAD) + (j+1)*KPAD + hf*8)*2);
            cp16(d + OFF_XSH, g_xth + s);
            cp16(d + OFF_XSL, g_xtl + s);
        }
    }
    // w: 9 taps x 64 oc x (2 half16)
    size_t wbase = (((size_t)(b*NCK + ck)) * TAPS) * OCH * 16;
    for (int i = tid; i < TAPS*CTA_M*2; i += 256) {
        int tap = i >> 7, rem = i & 127;
        int oc = rem >> 1, hf = rem & 1;
        size_t s = wbase + ((size_t)tap*OCH + oc0 + oc)*16 + hf*8;
        uint32_t d = stg + (uint32_t)((tap*(CTA_M*KPAD) + oc*KPAD + hf*8)*2);
        cp16(d + OFF_WSH, g_wkh + s);
        cp16(d + OFF_WSL, g_wkl + s);
    }
    cp_commit();
}

__global__ void __launch_bounds__(256, 1)
conv_mma(float* __restrict__ y) {
    extern __shared__ char smem[];
    const int oc0     = blockIdx.x * CTA_M;
    const int rowbase = blockIdx.y * 8;
    const int b       = blockIdx.z;
    const int tid = threadIdx.x, wid = tid >> 5, lane = tid & 31;
    const int gid = lane >> 2, q = lane & 3;
    const int mg = wid >> 2;            // 0..1 : 32-oc group
    const int ng = wid & 3;             // 0..3 : 2-row group
    const uint32_t sb = smem_u32(smem);

    // zero both stages (halo cells must be 0 and are never overwritten)
    {
        float4 z = make_float4(0.f,0.f,0.f,0.f);
        float4* p = (float4*)smem;
        for (int i = tid; i < SMEM_TOTAL/16; i += 256) p[i] = z;
    }
    __syncthreads();

    float acc[2][14][4];
#pragma unroll
    for (int a = 0; a < 2; a++)
#pragma unroll
        for (int n = 0; n < 14; n++)
#pragma unroll
            for (int k = 0; k < 4; k++) acc[a][n][k] = 0.f;

    issue_chunk(b, 0, rowbase, oc0, tid, sb);

    for (int ck = 0; ck < NCK; ck++) {
        const int s = ck & 1;
        if (ck + 1 < NCK)
            issue_chunk(b, ck+1, rowbase, oc0, tid, sb + (s^1)*STAGE_BYTES);
        if (ck + 1 < NCK) cp_wait<1>(); else cp_wait<0>();
        __syncthreads();

        const char* stg = smem + s*STAGE_BYTES;
        const __half* xs_h = (const __half*)(stg + OFF_XSH);
        const __half* xs_l = (const __half*)(stg + OFF_XSL);
        const __half* ws_h = (const __half*)(stg + OFF_WSH);
        const __half* ws_l = (const __half*)(stg + OFF_WSL);

#pragma unroll 1
        for (int tap = 0; tap < TAPS; tap++) {
            const int dy = tap / 3, dx = tap - dy*3;
            // A fragments: 2 m-tiles, hi+lo. PTX m16n8k16 A mapping:
            // a0=A[g][2q,+1] a1=A[g+8][2q,+1] a2=A[g][2q+8,+1] a3=A[g+8][2q+8,+1]
            uint32_t ah[2][4], al[2][4];
#pragma unroll
            for (int mt = 0; mt < 2; mt++) {
                int ocr = mg*32 + mt*16 + gid;
                int base = tap*(CTA_M*KPAD) + ocr*KPAD;
                ah[mt][0] = *(const uint32_t*)(ws_h + base + q*2);
                ah[mt][1] = *(const uint32_t*)(ws_h + base + 8*KPAD + q*2);
                ah[mt][2] = *(const uint32_t*)(ws_h + base + q*2 + 8);
                ah[mt][3] = *(const uint32_t*)(ws_h + base + 8*KPAD + q*2 + 8);
                al[mt][0] = *(const uint32_t*)(ws_l + base + q*2);
                al[mt][1] = *(const uint32_t*)(ws_l + base + 8*KPAD + q*2);
                al[mt][2] = *(const uint32_t*)(ws_l + base + q*2 + 8);
                al[mt][3] = *(const uint32_t*)(ws_l + base + 8*KPAD + q*2 + 8);
            }
#pragma unroll
            for (int rl = 0; rl < 2; rl++) {
                const int xrow = ng*2 + rl + dy;            // 0..9
#pragma unroll
                for (int ct = 0; ct < 7; ct++) {
                    // B mapping: b0=B[2q,+1][g]  b1=B[2q+8,+1][g]
                    int jb = (xrow*58 + ct*8 + dx + gid) * KPAD;
                    uint32_t bh0 = *(const uint32_t*)(xs_h + jb + q*2);
                    uint32_t bh1 = *(const uint32_t*)(xs_h + jb + q*2 + 8);
                    uint32_t bl0 = *(const uint32_t*)(xs_l + jb + q*2);
                    uint32_t bl1 = *(const uint32_t*)(xs_l + jb + q*2 + 8);
                    const int nt = rl*7 + ct;
#pragma unroll
                    for (int mt = 0; mt < 2; mt++) {
                        mma16816(acc[mt][nt], ah[mt], bh0, bh1);
                        mma16816(acc[mt][nt], al[mt], bh0, bh1);
                        mma16816(acc[mt][nt], ah[mt], bl0, bl1);
                    }
                }
            }
        }
        __syncthreads();   // all reads of stage s done before it is refilled
    }

    // epilogue: C mapping c0,c1=C[g][2q,+1]; c2,c3=C[g+8][2q,+1]
#pragma unroll
    for (int mt = 0; mt < 2; mt++) {
        int oc = oc0 + mg*32 + mt*16 + gid;
#pragma unroll
        for (int rl = 0; rl < 2; rl++) {
            int row = rowbase + ng*2 + rl;
#pragma unroll
            for (int ct = 0; ct < 7; ct++) {
                const int nt = rl*7 + ct;
                int col = ct*8 + q*2;
                float* yp = y + ((size_t)(b*OCH + oc)*HW + row)*HW + col;
                *(float2*)yp = make_float2(acc[mt][nt][0], acc[mt][nt][1]);
                *(float2*)(yp + 8*NPIX) = make_float2(acc[mt][nt][2], acc[mt][nt][3]);
            }
        }
    }
}

// ---------------------------------------------------------------------------
extern "C" void kernel_launch(void* const* d_in, const int* in_sizes, int n_in,
                              void* d_out, int out_size) {
    const float* x        = (const float*)d_in[0];
    const float* reduce_w = (const float*)d_in[1];
    const float* reduce_b = (const float*)d_in[2];
    const float* fc1_w    = (const float*)d_in[3];
    const float* fc2_w    = (const float*)d_in[4];
    const float* fc2_b    = (const float*)d_in[5];
    float* y = (float*)d_out;

    cudaFuncSetAttribute(conv_mma,
                         cudaFuncAttributeMaxDynamicSharedMemorySize, SMEM_TOTAL);

    gap_kernel<<<1024, 256>>>(x);
    se_kernel<<<1, 512>>>(reduce_w, reduce_b, fc1_w);
    wk_kernel<<<73728, 256>>>(fc2_w, fc2_b);                 // 18.87M items
    dim3 xg(14, NCK, BATCH);
    xt_kernel<<<xg, 256>>>(x);
    dim3 grid(4, 7, BATCH);
    conv_mma<<<grid, 256, SMEM_TOTAL>>>(y);
}

// round 8
// speedup vs baseline: 3.7204x; 1.3799x over previous
#include <cuda_runtime.h>
#include <cuda_fp16.h>
#include <math.h>
#include <stdint.h>

#define BATCH 32
#define CIN   256
#define OCH   256
#define HW    56
#define NPIX  3136
#define GAPN  16
#define MOCH  512
#define NCK   16          // 16 channel-chunks of 16
#define TAPS  9

// conv CTA tiling: 64 oc x (8 rows x 56 cols) per batch
#define CTA_M 64
#define KPAD  24          // k-dim padded 16->24 halves (16B-aligned ldmatrix rows)

// smem stage layout (bytes): x hi | w hi | w lo
#define XS_BYTES (10*58*KPAD*2)                 // 27840
#define WS_BYTES (TAPS*CTA_M*KPAD*2)            // 27648
#define OFF_XSH 0
#define OFF_WSH (XS_BYTES)
#define OFF_WSL (XS_BYTES + WS_BYTES)
#define STAGE_BYTES (XS_BYTES + 2*WS_BYTES)     // 83136
#define SMEM_TOTAL  (2*STAGE_BYTES)             // 166272

__device__ float  g_gap[BATCH*CIN];
__device__ float  g_a[BATCH*MOCH];
__device__ __half g_xth[(size_t)BATCH*NCK*NPIX*16];       // 51.4 MB
__device__ __half g_wkh[(size_t)BATCH*NCK*TAPS*OCH*16];   // 37.7 MB
__device__ __half g_wkl[(size_t)BATCH*NCK*TAPS*OCH*16];

// ---- helpers --------------------------------------------------------------
__device__ __forceinline__ uint32_t smem_u32(const void* p) {
    uint32_t a;
    asm("{ .reg .u64 t; cvta.to.shared.u64 t, %1; cvt.u32.u64 %0, t; }"
        : "=r"(a) : "l"(p));
    return a;
}
__device__ __forceinline__ void cp16(uint32_t dst, const void* src) {
    asm volatile("cp.async.cg.shared.global [%0], [%1], 16;"
                 :: "r"(dst), "l"(src) : "memory");
}
__device__ __forceinline__ void cp_commit() {
    asm volatile("cp.async.commit_group;" ::: "memory");
}
template <int N>
__device__ __forceinline__ void cp_wait() {
    asm volatile("cp.async.wait_group %0;" :: "n"(N) : "memory");
}
__device__ __forceinline__ void mma16816(float* c, const uint32_t* a,
                                         uint32_t b0, uint32_t b1) {
    asm volatile(
        "mma.sync.aligned.m16n8k16.row.col.f32.f16.f16.f32 "
        "{%0,%1,%2,%3}, {%4,%5,%6,%7}, {%8,%9}, {%0,%1,%2,%3};"
        : "+f"(c[0]), "+f"(c[1]), "+f"(c[2]), "+f"(c[3])
        : "r"(a[0]), "r"(a[1]), "r"(a[2]), "r"(a[3]), "r"(b0), "r"(b1));
}
__device__ __forceinline__ void ldmx4(uint32_t* r, uint32_t addr) {
    asm volatile("ldmatrix.sync.aligned.m8n8.x4.shared.b16 {%0,%1,%2,%3}, [%4];"
                 : "=r"(r[0]), "=r"(r[1]), "=r"(r[2]), "=r"(r[3]) : "r"(addr));
}
__device__ __forceinline__ void ldmx2(uint32_t& r0, uint32_t& r1, uint32_t addr) {
    asm volatile("ldmatrix.sync.aligned.m8n8.x2.shared.b16 {%0,%1}, [%2];"
                 : "=r"(r0), "=r"(r1) : "r"(addr));
}

// ---------------------------------------------------------------------------
// A: global average pool (one warp per (b,c))
// ---------------------------------------------------------------------------
__global__ void gap_kernel(const float* __restrict__ x) {
    int warp = (blockIdx.x * blockDim.x + threadIdx.x) >> 5;
    int lane = threadIdx.x & 31;
    if (warp >= BATCH*CIN) return;
    const float* p = x + (size_t)warp * NPIX;
    float s = 0.f;
#pragma unroll
    for (int i = 0; i < 98; i++) s += p[lane + i*32];
#pragma unroll
    for (int o = 16; o > 0; o >>= 1) s += __shfl_xor_sync(0xffffffffu, s, o);
    if (lane == 0) g_gap[warp] = s * (1.0f / (float)NPIX);
}

// ---------------------------------------------------------------------------
// B: reduce + fc1 + sigmoid
// ---------------------------------------------------------------------------
__global__ void se_kernel(const float* __restrict__ reduce_w,
                          const float* __restrict__ reduce_b,
                          const float* __restrict__ fc1_w) {
    __shared__ float sg[BATCH*GAPN];
    int tid = threadIdx.x;
    {
        int b = tid >> 4, j = tid & 15;
        float s = reduce_b[j];
        const float* gp = g_gap + b*CIN;
        const float* wp = reduce_w + j*CIN;
#pragma unroll 8
        for (int c = 0; c < CIN; c++) s += gp[c] * wp[c];
        sg[b*GAPN + j] = s;
    }
    __syncthreads();
    {
        int mo = tid;
        float w[GAPN];
#pragma unroll
        for (int j = 0; j < GAPN; j++) w[j] = fc1_w[mo*GAPN + j];
        for (int b = 0; b < BATCH; b++) {
            float s = 0.f;
#pragma unroll
            for (int j = 0; j < GAPN; j++) s += sg[b*GAPN + j] * w[j];
            g_a[b*MOCH + mo] = 1.0f / (1.0f + expf(-s));
        }
    }
}

// ---------------------------------------------------------------------------
// C: x transpose to [b][ck][px][c16] fp16 (hi only; x-lo term dropped)
// ---------------------------------------------------------------------------
__global__ void xt_kernel(const float* __restrict__ x) {
    __shared__ float tile[16*225];
    const int rblk = blockIdx.x, ck = blockIdx.y, b = blockIdx.z;
    const int tid = threadIdx.x;
    for (int i = tid; i < 16*224; i += 256) {
        int c = i / 224, p = i - c*224;
        tile[c*225 + p] =
            x[((size_t)(b*CIN) + ck*16 + c)*NPIX + rblk*224 + p];
    }
    __syncthreads();
    size_t base = ((size_t)(b*NCK + ck)*NPIX + rblk*224) * 16;
    for (int i = tid; i < 16*224; i += 256) {
        int p = i >> 4, c = i & 15;
        g_xth[base + p*16 + c] = __float2half_rn(tile[c*225 + p]);
    }
}

// ---------------------------------------------------------------------------
// D: weight materialize to [b][ck][tap][oc][c16] fp16 hi/lo
// ---------------------------------------------------------------------------
__global__ void wk_kernel(const float* __restrict__ fc2_w,
                          const float* __restrict__ fc2_b) {
    size_t idx = (size_t)blockIdx.x * 256 + threadIdx.x;
    int c  = (int)(idx & 15);
    size_t r1 = idx >> 4;
    int oc = (int)(r1 & 255);
    size_t r2 = r1 >> 8;
    int tap = (int)(r2 % 9);
    size_t r3 = r2 / 9;
    int ck = (int)(r3 & 15);
    int b  = (int)(r3 >> 4);
    int cg = ck*16 + c;
    float a = g_a[b*MOCH + 2*oc + (cg >= 128 ? 1 : 0)];
    int f = oc*2304 + cg*9 + tap;
    float w = fmaf(a, fc2_w[f], fc2_b[f]);
    __half h = __float2half_rn(w);
    __half l = __float2half_rn(w - __half2float(h));
    g_wkh[idx] = h;
    g_wkl[idx] = l;
}

// ---------------------------------------------------------------------------
// E: tensor-core conv. grid (4 ocq, 7 rowgrp, 32 b), 256 thr.
// ---------------------------------------------------------------------------
__device__ __forceinline__ void issue_chunk(int b, int ck, int rowbase,
                                            int oc0, int tid, uint32_t stg) {
    // x hi: 10 rows x 56 cols x (2 x 16B); invalid rows stay zero
    size_t xbase = ((size_t)(b*NCK + ck)) * NPIX * 16;
    for (int i = tid; i < 10*56*2; i += 256) {
        int r = i / 112, rem = i - r*112;
        int j = rem >> 1, hf = rem & 1;
        int ar = rowbase + r - 1;
        if ((unsigned)ar < (unsigned)HW) {
            size_t s = xbase + ((size_t)ar*HW + j)*16 + hf*8;
            uint32_t d = stg + (uint32_t)((r*(58*KPAD) + (j+1)*KPAD + hf*8)*2);
            cp16(d + OFF_XSH, g_xth + s);
        }
    }
    // w hi/lo: 9 taps x 64 oc x (2 x 16B)
    size_t wbase = (((size_t)(b*NCK + ck)) * TAPS) * OCH * 16;
    for (int i = tid; i < TAPS*CTA_M*2; i += 256) {
        int tap = i >> 7, rem = i & 127;
        int oc = rem >> 1, hf = rem & 1;
        size_t s = wbase + ((size_t)tap*OCH + oc0 + oc)*16 + hf*8;
        uint32_t d = stg + (uint32_t)((tap*(CTA_M*KPAD) + oc*KPAD + hf*8)*2);
        cp16(d + OFF_WSH, g_wkh + s);
        cp16(d + OFF_WSL, g_wkl + s);
    }
    cp_commit();
}

__global__ void __launch_bounds__(256, 1)
conv_mma(float* __restrict__ y) {
    extern __shared__ char smem[];
    const int oc0     = blockIdx.x * CTA_M;
    const int rowbase = blockIdx.y * 8;
    const int b       = blockIdx.z;
    const int tid = threadIdx.x, wid = tid >> 5, lane = tid & 31;
    const int gid = lane >> 2, q = lane & 3;
    const int mg = wid >> 2;            // 0..1 : 32-oc group
    const int ng = wid & 3;             // 0..3 : 2-row group
    const uint32_t sb = smem_u32(smem);

    // ldmatrix lane-constant address parts
    const int lm = lane >> 3, lr = lane & 7;
    // A (x4): matrices (rows0-7,k0)(rows8-15,k0)(rows0-7,k8)(rows8-15,k8)
    const uint32_t aoff =
        (uint32_t)(((mg*32 + ((lm & 1) << 3) + lr)*KPAD + ((lm >> 1) << 3)) * 2);
    // B (x2): matrices (px0-7,k0)(px0-7,k8); lanes 16-31 unused (valid addr)
    const uint32_t boff = (uint32_t)((lr*KPAD + ((lm & 1) << 3)) * 2);

    // zero both stages (halo cells must be 0 and are never overwritten)
    {
        float4 z = make_float4(0.f,0.f,0.f,0.f);
        float4* p = (float4*)smem;
        for (int i = tid; i < SMEM_TOTAL/16; i += 256) p[i] = z;
    }
    __syncthreads();

    float acc[2][14][4];
#pragma unroll
    for (int a = 0; a < 2; a++)
#pragma unroll
        for (int n = 0; n < 14; n++)
#pragma unroll
            for (int k = 0; k < 4; k++) acc[a][n][k] = 0.f;

    issue_chunk(b, 0, rowbase, oc0, tid, sb);

    for (int ck = 0; ck < NCK; ck++) {
        const int s = ck & 1;
        if (ck + 1 < NCK)
            issue_chunk(b, ck+1, rowbase, oc0, tid, sb + (s^1)*STAGE_BYTES);
        if (ck + 1 < NCK) cp_wait<1>(); else cp_wait<0>();
        __syncthreads();

        const uint32_t st = sb + s*STAGE_BYTES;
        const uint32_t a_h = st + OFF_WSH + aoff;
        const uint32_t a_l = st + OFF_WSL + aoff;
        const uint32_t b_h = st + OFF_XSH + boff;

#pragma unroll 1
        for (int tap = 0; tap < TAPS; tap++) {
            const int dy = tap / 3, dx = tap - dy*3;
            uint32_t ah[2][4], al[2][4];
#pragma unroll
            for (int mt = 0; mt < 2; mt++) {
                uint32_t o = (uint32_t)((tap*CTA_M + mt*16)*KPAD*2);
                ldmx4(ah[mt], a_h + o);
                ldmx4(al[mt], a_l + o);
            }
#pragma unroll
            for (int rl = 0; rl < 2; rl++) {
                const int xrow = ng*2 + rl + dy;            // 0..9
                uint32_t baddr = b_h + (uint32_t)(((xrow*58 + dx)*KPAD)*2);
#pragma unroll
                for (int ct = 0; ct < 7; ct++) {
                    uint32_t b0, b1;
                    ldmx2(b0, b1, baddr + (uint32_t)(ct*8*KPAD*2));
                    const int nt = rl*7 + ct;
#pragma unroll
                    for (int mt = 0; mt < 2; mt++) {
                        mma16816(acc[mt][nt], ah[mt], b0, b1);
                        mma16816(acc[mt][nt], al[mt], b0, b1);
                    }
                }
            }
        }
        __syncthreads();   // all reads of stage s done before it is refilled
    }

    // epilogue: c0,c1 = C[g][2q,+1]; c2,c3 = C[g+8][2q,+1]
#pragma unroll
    for (int mt = 0; mt < 2; mt++) {
        int oc = oc0 + mg*32 + mt*16 + gid;
#pragma unroll
        for (int rl = 0; rl < 2; rl++) {
            int row = rowbase + ng*2 + rl;
#pragma unroll
            for (int ct = 0; ct < 7; ct++) {
                const int nt = rl*7 + ct;
                int col = ct*8 + q*2;
                float* yp = y + ((size_t)(b*OCH + oc)*HW + row)*HW + col;
                *(float2*)yp = make_float2(acc[mt][nt][0], acc[mt][nt][1]);
                *(float2*)(yp + 8*NPIX) = make_float2(acc[mt][nt][2], acc[mt][nt][3]);
            }
        }
    }
}

// ---------------------------------------------------------------------------
extern "C" void kernel_launch(void* const* d_in, const int* in_sizes, int n_in,
                              void* d_out, int out_size) {
    const float* x        = (const float*)d_in[0];
    const float* reduce_w = (const float*)d_in[1];
    const float* reduce_b = (const float*)d_in[2];
    const float* fc1_w    = (const float*)d_in[3];
    const float* fc2_w    = (const float*)d_in[4];
    const float* fc2_b    = (const float*)d_in[5];
    float* y = (float*)d_out;

    cudaFuncSetAttribute(conv_mma,
                         cudaFuncAttributeMaxDynamicSharedMemorySize, SMEM_TOTAL);

    gap_kernel<<<1024, 256>>>(x);
    se_kernel<<<1, 512>>>(reduce_w, reduce_b, fc1_w);
    wk_kernel<<<73728, 256>>>(fc2_w, fc2_b);                 // 18.87M items
    dim3 xg(14, NCK, BATCH);
    xt_kernel<<<xg, 256>>>(x);
    dim3 grid(4, 7, BATCH);
    conv_mma<<<grid, 256, SMEM_TOTAL>>>(y);
}